// round 4
// baseline (speedup 1.0000x reference)
#include <cuda_runtime.h>
#include <math.h>

#define NN 4096
#define NF 4096
#define NH 4
#define NO 8
#define NC32 32            // NH*NO
#define NW (NN/32)         // bitmask words per row = 128
#define GAT_ALPHA 0.2f
#define L2E 1.44269504088896341f

// ---------------- scratch (__device__ globals; no allocations) ----------------
__device__ float         g_Cpart[4][NN * NC32];   // k-split GEMM partials (2MB)
__device__ float         g_Wh[NN * NC32];         // Wh[j][h*8+o]  (512KB, L2-resident)
__device__ float         g_sdst4[NN * NH];        // s_dst[j][h]   (64KB)
__device__ float         g_ssrc4[NN * NH];        // s_src[i][h]
__device__ unsigned      g_bmT[NW * NN];          // bitmask, transposed: [jw][i] (2MB)
__device__ float         g_ml[NN * NH];           // lrelu(ssrc+maxsd)*log2(e) per (i,h)
__device__ float         g_hp[NN * NC32];         // h_prime[i][h*8+o]
__device__ float         g_ls[NN * NO];           // log_softmax(node_embeddings)

// ---------------- helpers ----------------
__device__ __forceinline__ void ffma2(unsigned long long& d, unsigned long long a,
                                      unsigned long long b) {
    asm("fma.rn.f32x2 %0, %1, %2, %0;" : "+l"(d) : "l"(a), "l"(b));
}
__device__ __forceinline__ unsigned long long pack2(float v) {
    unsigned long long r;
    asm("mov.b64 %0, {%1, %1};" : "=l"(r) : "f"(v));
    return r;
}
union U64F2 { unsigned long long u; float2 f; };

// ---------------- 1) pack adjacency into transposed bitmask ----------------
__global__ void k_pack(const int* __restrict__ adj) {
    int w = threadIdx.x >> 5, lane = threadIdx.x & 31;
    int i = blockIdx.x * 8 + w;
    const int* row = adj + (size_t)i * NN;
    for (int jw = 0; jw < NW; jw++) {
        int v = __ldg(row + jw * 32 + lane);
        unsigned word = __ballot_sync(0xffffffffu, v != 0);
        if (lane == 0) g_bmT[jw * NN + i] = word;
    }
}

// ---------------- 2) Wh = x @ Wc  (k-split x4, BM=64) ----------------
__global__ void k_gemm(const float* __restrict__ x, const float* __restrict__ W) {
    __shared__ float xs[64][40];
    __shared__ float ws[32][36];
    int t = threadIdx.x;
    int c = t & 31, rg = t >> 5;
    int row0 = blockIdx.x * 64;
    int kbase = blockIdx.y * (NF / 4);
    float acc[8];
#pragma unroll
    for (int r = 0; r < 8; r++) acc[r] = 0.f;

    for (int kt = 0; kt < NF / 4; kt += 32) {
        int k0 = kbase + kt;
#pragma unroll
        for (int q = 0; q < 2; q++) {
            int s = t * 2 + q;
            int r = s >> 3, kq = s & 7;
            float4 v = __ldg((const float4*)(x + (size_t)(row0 + r) * NF + k0 + kq * 4));
            *(float4*)&xs[r][kq * 4] = v;
        }
        {
            int k = t >> 3, c4 = (t & 7) * 4;
            int h = c4 >> 3, o = c4 & 7;
            float4 v = __ldg((const float4*)(W + (size_t)h * NF * NO + (size_t)(k0 + k) * NO + o));
            *(float4*)&ws[k][c4] = v;
        }
        __syncthreads();
#pragma unroll
        for (int k4 = 0; k4 < 32; k4 += 4) {
            float w0 = ws[k4][c], w1 = ws[k4 + 1][c], w2 = ws[k4 + 2][c], w3 = ws[k4 + 3][c];
#pragma unroll
            for (int r = 0; r < 8; r++) {
                float4 xv = *(const float4*)&xs[rg * 8 + r][k4];
                acc[r] = fmaf(xv.x, w0, acc[r]);
                acc[r] = fmaf(xv.y, w1, acc[r]);
                acc[r] = fmaf(xv.z, w2, acc[r]);
                acc[r] = fmaf(xv.w, w3, acc[r]);
            }
        }
        __syncthreads();
    }
    float* outp = g_Cpart[blockIdx.y];
#pragma unroll
    for (int r = 0; r < 8; r++)
        outp[(size_t)(row0 + rg * 8 + r) * NC32 + c] = acc[r];
}

// ---------------- 3) reduce k-split partials; compute s_src/s_dst ----------------
__global__ void k_whfin(const float* __restrict__ a) {
    int i = blockIdx.x * blockDim.x + threadIdx.x;   // one row per thread
    float v[32];
#pragma unroll
    for (int c4 = 0; c4 < 8; c4++) {
        float4 s = make_float4(0.f, 0.f, 0.f, 0.f);
#pragma unroll
        for (int ks = 0; ks < 4; ks++) {
            float4 p = *(const float4*)&g_Cpart[ks][(size_t)i * NC32 + c4 * 4];
            s.x += p.x; s.y += p.y; s.z += p.z; s.w += p.w;
        }
        v[c4 * 4 + 0] = s.x; v[c4 * 4 + 1] = s.y; v[c4 * 4 + 2] = s.z; v[c4 * 4 + 3] = s.w;
        *(float4*)&g_Wh[(size_t)i * NC32 + c4 * 4] = s;
    }
#pragma unroll
    for (int h = 0; h < NH; h++) {
        float ss = 0.f, sd = 0.f;
#pragma unroll
        for (int o = 0; o < NO; o++) {
            float wv = v[h * 8 + o];
            ss = fmaf(wv, __ldg(a + h * 16 + o), ss);
            sd = fmaf(wv, __ldg(a + h * 16 + 8 + o), sd);
        }
        g_ssrc4[i * NH + h] = ss;
        g_sdst4[i * NH + h] = sd;
    }
}

// ---------------- 4) masked row-max of s_dst  (lrelu is monotone) ----------------
__global__ void k_max() {
    int lane = threadIdx.x & 31, w = threadIdx.x >> 5;
    int i = blockIdx.x * 32 + lane;
    float M[4];
#pragma unroll
    for (int h = 0; h < 4; h++) M[h] = -INFINITY;

    for (int jw = w * (NW / 8); jw < (w + 1) * (NW / 8); jw++) {
        unsigned word = g_bmT[jw * NN + i];
        int jb = jw * 32;
#pragma unroll 8
        for (int b = 0; b < 32; b++) {
            float4 sd = __ldg((const float4*)(g_sdst4 + (size_t)(jb + b) * 4));
            if ((word >> b) & 1u) {
                M[0] = fmaxf(M[0], sd.x); M[1] = fmaxf(M[1], sd.y);
                M[2] = fmaxf(M[2], sd.z); M[3] = fmaxf(M[3], sd.w);
            }
        }
    }
    __shared__ float red[8][32][4];
#pragma unroll
    for (int h = 0; h < 4; h++) red[w][lane][h] = M[h];
    __syncthreads();
    if (threadIdx.x < 128) {
        int il = threadIdx.x & 31, h = threadIdx.x >> 5;
        float m = red[0][il][h];
#pragma unroll
        for (int ww = 1; ww < 8; ww++) m = fmaxf(m, red[ww][il][h]);
        int gi = blockIdx.x * 32 + il;
        float e = g_ssrc4[gi * NH + h] + m;
        e = fmaxf(e, GAT_ALPHA * e);
        g_ml[gi * NH + h] = e * L2E;
    }
}

// ---------------- 5) main attention pass ----------------
__global__ void k_attn() {
    int lane = threadIdx.x & 31, w = threadIdx.x >> 5;
    int i = blockIdx.x * 32 + lane;
    float ss[4], ml[4];
#pragma unroll
    for (int h = 0; h < 4; h++) { ss[h] = g_ssrc4[i * 4 + h]; ml[h] = g_ml[i * 4 + h]; }

    unsigned long long acc[4][4];
    float Z[4];
#pragma unroll
    for (int h = 0; h < 4; h++) {
        Z[h] = 0.f;
#pragma unroll
        for (int q = 0; q < 4; q++) acc[h][q] = 0ull;
    }

    for (int jw = w * (NW / 8); jw < (w + 1) * (NW / 8); jw++) {
        unsigned word = g_bmT[jw * NN + i];
        int jb = jw * 32;
#pragma unroll 4
        for (int b = 0; b < 32; b++) {
            int j = jb + b;
            float4 sd = __ldg((const float4*)(g_sdst4 + (size_t)j * 4));  // broadcast
            unsigned on = (word >> b) & 1u;
#pragma unroll
            for (int h = 0; h < 4; h++) {
                float sdh = (h == 0) ? sd.x : (h == 1) ? sd.y : (h == 2) ? sd.z : sd.w;
                float e = ss[h] + sdh;
                e = fmaxf(e, GAT_ALPHA * e);           // leaky relu
                float t = fmaf(e, L2E, -ml[h]);        // (e - m) * log2(e)
                float wt;
                asm("ex2.approx.ftz.f32 %0, %1;" : "=f"(wt) : "f"(t));
                wt = on ? wt : 0.0f;
                Z[h] += wt;
                unsigned long long w2 = pack2(wt);
                const ulonglong2* wp =
                    (const ulonglong2*)(g_Wh) + ((size_t)j * 8 + h * 2);
                ulonglong2 wa = __ldg(wp);             // broadcast, 8 floats of Wh
                ulonglong2 wb = __ldg(wp + 1);
                ffma2(acc[h][0], w2, wa.x);
                ffma2(acc[h][1], w2, wa.y);
                ffma2(acc[h][2], w2, wb.x);
                ffma2(acc[h][3], w2, wb.y);
            }
        }
    }

    __shared__ float red[8][32][36];
    {
        float* rp = red[w][lane];
#pragma unroll
        for (int h = 0; h < 4; h++) {
#pragma unroll
            for (int q = 0; q < 4; q++) {
                U64F2 cv; cv.u = acc[h][q];
                rp[h * 9 + q * 2]     = cv.f.x;
                rp[h * 9 + q * 2 + 1] = cv.f.y;
            }
            rp[h * 9 + 8] = Z[h];
        }
    }
    __syncthreads();
    if (threadIdx.x < 128) {
        int il = threadIdx.x & 31, h = threadIdx.x >> 5;
        float s[9];
#pragma unroll
        for (int q = 0; q < 9; q++) s[q] = 0.f;
#pragma unroll
        for (int ww = 0; ww < 8; ww++) {
            const float* rp = red[ww][il];
#pragma unroll
            for (int q = 0; q < 9; q++) s[q] += rp[h * 9 + q];
        }
        float zi = 1.0f / fmaxf(s[8], 1e-30f);
        int gi = blockIdx.x * 32 + il;
        float4 o0 = make_float4(s[0] * zi, s[1] * zi, s[2] * zi, s[3] * zi);
        float4 o1 = make_float4(s[4] * zi, s[5] * zi, s[6] * zi, s[7] * zi);
        *(float4*)&g_hp[(size_t)gi * NC32 + h * 8]     = o0;
        *(float4*)&g_hp[(size_t)gi * NC32 + h * 8 + 4] = o1;
    }
}

// ---------------- 6) node embeddings + log_softmax ----------------
__global__ void k_fin1(float* __restrict__ dne, int write_ne) {
    int i = blockIdx.x * blockDim.x + threadIdx.x;
    float ne[8];
#pragma unroll
    for (int o = 0; o < 8; o++) ne[o] = 0.f;
#pragma unroll
    for (int h = 0; h < 4; h++) {
        float4 a0 = *(const float4*)&g_hp[(size_t)i * NC32 + h * 8];
        float4 a1 = *(const float4*)&g_hp[(size_t)i * NC32 + h * 8 + 4];
        ne[0] += a0.x; ne[1] += a0.y; ne[2] += a0.z; ne[3] += a0.w;
        ne[4] += a1.x; ne[5] += a1.y; ne[6] += a1.z; ne[7] += a1.w;
    }
#pragma unroll
    for (int o = 0; o < 8; o++) ne[o] *= 0.25f;
    float m = ne[0];
#pragma unroll
    for (int o = 1; o < 8; o++) m = fmaxf(m, ne[o]);
    float sum = 0.f;
#pragma unroll
    for (int o = 0; o < 8; o++) sum += expf(ne[o] - m);
    float lse = logf(sum) + m;
#pragma unroll
    for (int o = 0; o < 8; o++) g_ls[(size_t)i * NO + o] = ne[o] - lse;
    if (write_ne) {
#pragma unroll
        for (int o = 0; o < 8; o++) dne[(size_t)i * NO + o] = ne[o];
    }
}

// ---------------- 7) out = ls.T @ w_lin.T + b ----------------
__global__ void k_fin2(const float* __restrict__ wl, const float* __restrict__ bl,
                       float* __restrict__ dout, int write_out) {
    __shared__ float rb[256][8];
    int t = threadIdx.x;
    float p[8];
#pragma unroll
    for (int o = 0; o < 8; o++) p[o] = 0.f;
    for (int i = t; i < NN; i += 256) {
        float wv = __ldg(wl + i);
        float4 l0 = *(const float4*)&g_ls[(size_t)i * NO];
        float4 l1 = *(const float4*)&g_ls[(size_t)i * NO + 4];
        p[0] = fmaf(l0.x, wv, p[0]); p[1] = fmaf(l0.y, wv, p[1]);
        p[2] = fmaf(l0.z, wv, p[2]); p[3] = fmaf(l0.w, wv, p[3]);
        p[4] = fmaf(l1.x, wv, p[4]); p[5] = fmaf(l1.y, wv, p[5]);
        p[6] = fmaf(l1.z, wv, p[6]); p[7] = fmaf(l1.w, wv, p[7]);
    }
#pragma unroll
    for (int o = 0; o < 8; o++) rb[t][o] = p[o];
    __syncthreads();
    if (t < 8 && write_out) {
        float s = 0.f;
        for (int q = 0; q < 256; q++) s += rb[q][t];
        dout[t] = s + __ldg(bl);
    }
}

// ---------------- launch ----------------
extern "C" void kernel_launch(void* const* d_in, const int* in_sizes, int n_in,
                              void* d_out, int out_size) {
    const float* x   = (const float*)d_in[0];
    const int*   adj = (const int*)d_in[1];
    const float* W   = (const float*)d_in[2];
    const float* a   = (const float*)d_in[3];
    const float* wl  = (const float*)d_in[4];
    const float* bl  = (const float*)d_in[5];
    float* outp = (float*)d_out;

    int write_out = 0, write_ne = 0, ne_off = 0;
    if (out_size >= 8 + NN * NO)      { write_out = 1; write_ne = 1; ne_off = 8; }
    else if (out_size == NN * NO)     { write_ne = 1; ne_off = 0; }
    else                              { write_out = 1; }

    k_pack<<<NN / 8, 256>>>(adj);
    dim3 gg(NN / 64, 4);
    k_gemm<<<gg, 256>>>(x, W);
    k_whfin<<<NN / 256, 256>>>(a);
    k_max<<<NN / 32, 256>>>();
    k_attn<<<NN / 32, 256>>>();
    k_fin1<<<NN / 256, 256>>>(outp + ne_off, write_ne);
    k_fin2<<<1, 256>>>(wl, bl, outp, write_out);
}

// round 5
// speedup vs baseline: 1.5263x; 1.5263x over previous
#include <cuda_runtime.h>
#include <math.h>

#define NN 4096
#define NF 4096
#define NH 4
#define NO 8
#define NC32 32            // NH*NO
#define NW (NN/32)         // bitmask words per row = 128
#define JS 4               // j-splits for attention
#define KS 8               // k-splits for gemm
#define GAT_ALPHA 0.2f
#define L2E 1.44269504088896341f

// ---------------- scratch (__device__ globals; no allocations) ----------------
__device__ float         g_Cpart[KS][NN * NC32];  // k-split GEMM partials (4MB)
__device__ float         g_Wh[NN * NC32];         // Wh[j][h*8+o]  (512KB, L2-resident)
__device__ float         g_sdst4[NN * NH];        // s_dst[j][h]
__device__ float         g_ssrc4[NN * NH];        // s_src[i][h]
__device__ unsigned      g_bmT[NW * NN];          // bitmask, transposed: [jw][i] (2MB)
__device__ unsigned      g_maxsd[NH];             // global max of s_dst per head (keyed)
__device__ float         g_accp[JS][NN * NC32];   // attention partial accumulators (2MB)
__device__ float         g_zp[JS][NN * NH];       // attention partial Z
__device__ float         g_ls[NN * NO];           // log_softmax(node_embeddings)

// ---------------- helpers ----------------
__device__ __forceinline__ void ffma2(unsigned long long& d, unsigned long long a,
                                      unsigned long long b) {
    asm("fma.rn.f32x2 %0, %1, %2, %0;" : "+l"(d) : "l"(a), "l"(b));
}
__device__ __forceinline__ unsigned long long pack2(float v) {
    unsigned long long r;
    asm("mov.b64 %0, {%1, %1};" : "=l"(r) : "f"(v));
    return r;
}
union U64F2 { unsigned long long u; float2 f; };

// monotonic float<->uint key for atomicMax over signed floats
__device__ __forceinline__ unsigned fkey(float f) {
    unsigned u = __float_as_uint(f);
    return (u & 0x80000000u) ? ~u : (u | 0x80000000u);
}
__device__ __forceinline__ float funkey(unsigned k) {
    return __uint_as_float((k & 0x80000000u) ? (k & 0x7FFFFFFFu) : ~k);
}

// ---------------- 1) pack adjacency into transposed bitmask ----------------
__global__ void k_pack(const int* __restrict__ adj) {
    if (blockIdx.x == 0 && threadIdx.x < NH) g_maxsd[threadIdx.x] = 0u;  // reset per launch
    int w = threadIdx.x >> 5, lane = threadIdx.x & 31;
    int i = blockIdx.x * 8 + w;
    const int* row = adj + (size_t)i * NN;
    for (int jw = 0; jw < NW; jw++) {
        int v = __ldg(row + jw * 32 + lane);
        unsigned word = __ballot_sync(0xffffffffu, v != 0);
        if (lane == 0) g_bmT[jw * NN + i] = word;
    }
}

// ---------------- 2) Wh = x @ Wc  (k-split x8, BM=64) ----------------
__global__ void k_gemm(const float* __restrict__ x, const float* __restrict__ W) {
    __shared__ float xs[64][40];
    __shared__ float ws[32][36];
    int t = threadIdx.x;
    int c = t & 31, rg = t >> 5;
    int row0 = blockIdx.x * 64;
    int kbase = blockIdx.y * (NF / KS);
    float acc[8];
#pragma unroll
    for (int r = 0; r < 8; r++) acc[r] = 0.f;

    for (int kt = 0; kt < NF / KS; kt += 32) {
        int k0 = kbase + kt;
#pragma unroll
        for (int q = 0; q < 2; q++) {
            int s = t * 2 + q;
            int r = s >> 3, kq = s & 7;
            float4 v = __ldg((const float4*)(x + (size_t)(row0 + r) * NF + k0 + kq * 4));
            *(float4*)&xs[r][kq * 4] = v;
        }
        {
            int k = t >> 3, c4 = (t & 7) * 4;
            int h = c4 >> 3, o = c4 & 7;
            float4 v = __ldg((const float4*)(W + (size_t)h * NF * NO + (size_t)(k0 + k) * NO + o));
            *(float4*)&ws[k][c4] = v;
        }
        __syncthreads();
#pragma unroll
        for (int k4 = 0; k4 < 32; k4 += 4) {
            float w0 = ws[k4][c], w1 = ws[k4 + 1][c], w2 = ws[k4 + 2][c], w3 = ws[k4 + 3][c];
#pragma unroll
            for (int r = 0; r < 8; r++) {
                float4 xv = *(const float4*)&xs[rg * 8 + r][k4];
                acc[r] = fmaf(xv.x, w0, acc[r]);
                acc[r] = fmaf(xv.y, w1, acc[r]);
                acc[r] = fmaf(xv.z, w2, acc[r]);
                acc[r] = fmaf(xv.w, w3, acc[r]);
            }
        }
        __syncthreads();
    }
    float* outp = g_Cpart[blockIdx.y];
#pragma unroll
    for (int r = 0; r < 8; r++)
        outp[(size_t)(row0 + rg * 8 + r) * NC32 + c] = acc[r];
}

// ---------------- 3) reduce k-split partials; s_src/s_dst; global sd max ----------------
__global__ void k_whfin(const float* __restrict__ a) {
    int i = blockIdx.x * blockDim.x + threadIdx.x;   // one row per thread
    int lane = threadIdx.x & 31, w = threadIdx.x >> 5;
    float v[32];
#pragma unroll
    for (int c4 = 0; c4 < 8; c4++) {
        float4 s = make_float4(0.f, 0.f, 0.f, 0.f);
#pragma unroll
        for (int ks = 0; ks < KS; ks++) {
            float4 p = *(const float4*)&g_Cpart[ks][(size_t)i * NC32 + c4 * 4];
            s.x += p.x; s.y += p.y; s.z += p.z; s.w += p.w;
        }
        v[c4 * 4 + 0] = s.x; v[c4 * 4 + 1] = s.y; v[c4 * 4 + 2] = s.z; v[c4 * 4 + 3] = s.w;
        *(float4*)&g_Wh[(size_t)i * NC32 + c4 * 4] = s;
    }
    float sdv[NH];
#pragma unroll
    for (int h = 0; h < NH; h++) {
        float ss = 0.f, sd = 0.f;
#pragma unroll
        for (int o = 0; o < NO; o++) {
            float wv = v[h * 8 + o];
            ss = fmaf(wv, __ldg(a + h * 16 + o), ss);
            sd = fmaf(wv, __ldg(a + h * 16 + 8 + o), sd);
        }
        g_ssrc4[i * NH + h] = ss;
        g_sdst4[i * NH + h] = sd;
        sdv[h] = sd;
    }
    // block-reduce max(sd) per head -> atomicMax on keyed uint
    __shared__ float mred[NH][8];
#pragma unroll
    for (int h = 0; h < NH; h++) {
        float m = sdv[h];
#pragma unroll
        for (int off = 16; off > 0; off >>= 1)
            m = fmaxf(m, __shfl_xor_sync(0xffffffffu, m, off));
        if (lane == 0) mred[h][w] = m;
    }
    __syncthreads();
    if (threadIdx.x < NH) {
        int h = threadIdx.x;
        float m = mred[h][0];
#pragma unroll
        for (int ww = 1; ww < 8; ww++) m = fmaxf(m, mred[h][ww]);
        atomicMax(&g_maxsd[h], fkey(m));
    }
}

// ---------------- 4) main attention pass (j-split x4) ----------------
__global__ void __launch_bounds__(256) k_attn() {
    int lane = threadIdx.x & 31, w = threadIdx.x >> 5;
    int i = blockIdx.x * 32 + lane;
    int js = blockIdx.y;
    float ss[4], ml[4];
#pragma unroll
    for (int h = 0; h < 4; h++) {
        ss[h] = g_ssrc4[i * 4 + h];
        float M = funkey(g_maxsd[h]);         // global (unmasked) upper bound of sd
        float e = ss[h] + M;
        e = fmaxf(e, GAT_ALPHA * e);          // lrelu monotone -> valid softmax shift
        ml[h] = e * L2E;
    }

    unsigned long long acc[4][4];
    float Z[4];
#pragma unroll
    for (int h = 0; h < 4; h++) {
        Z[h] = 0.f;
#pragma unroll
        for (int q = 0; q < 4; q++) acc[h][q] = 0ull;
    }

    int jw0 = js * (NW / JS) + w * (NW / JS / 8);   // 4 words per warp
    for (int jw = jw0; jw < jw0 + (NW / JS / 8); jw++) {
        unsigned word = g_bmT[jw * NN + i];
        int jb = jw * 32;
#pragma unroll 8
        for (int b = 0; b < 32; b++) {
            int j = jb + b;
            float4 sd = __ldg((const float4*)(g_sdst4 + (size_t)j * 4));  // broadcast
            unsigned on = (word >> b) & 1u;
#pragma unroll
            for (int h = 0; h < 4; h++) {
                float sdh = (h == 0) ? sd.x : (h == 1) ? sd.y : (h == 2) ? sd.z : sd.w;
                float e = ss[h] + sdh;
                e = fmaxf(e, GAT_ALPHA * e);           // leaky relu
                float t = fmaf(e, L2E, -ml[h]);        // (e - m) * log2(e)
                float wt;
                asm("ex2.approx.ftz.f32 %0, %1;" : "=f"(wt) : "f"(t));
                wt = on ? wt : 0.0f;
                Z[h] += wt;
                unsigned long long w2 = pack2(wt);
                const ulonglong2* wp =
                    (const ulonglong2*)(g_Wh) + ((size_t)j * 8 + h * 2);
                ulonglong2 wa = __ldg(wp);             // broadcast, 8 floats of Wh
                ulonglong2 wb = __ldg(wp + 1);
                ffma2(acc[h][0], w2, wa.x);
                ffma2(acc[h][1], w2, wa.y);
                ffma2(acc[h][2], w2, wb.x);
                ffma2(acc[h][3], w2, wb.y);
            }
        }
    }

    __shared__ float red[8][32][36];
    {
        float* rp = red[w][lane];
#pragma unroll
        for (int h = 0; h < 4; h++) {
#pragma unroll
            for (int q = 0; q < 4; q++) {
                U64F2 cv; cv.u = acc[h][q];
                rp[h * 9 + q * 2]     = cv.f.x;
                rp[h * 9 + q * 2 + 1] = cv.f.y;
            }
            rp[h * 9 + 8] = Z[h];
        }
    }
    __syncthreads();
    if (threadIdx.x < 128) {
        int il = threadIdx.x & 31, h = threadIdx.x >> 5;
        float s[9];
#pragma unroll
        for (int q = 0; q < 9; q++) s[q] = 0.f;
#pragma unroll
        for (int ww = 0; ww < 8; ww++) {
            const float* rp = red[ww][il];
#pragma unroll
            for (int q = 0; q < 9; q++) s[q] += rp[h * 9 + q];
        }
        int gi = blockIdx.x * 32 + il;
        float4 o0 = make_float4(s[0], s[1], s[2], s[3]);
        float4 o1 = make_float4(s[4], s[5], s[6], s[7]);
        *(float4*)&g_accp[js][(size_t)gi * NC32 + h * 8]     = o0;
        *(float4*)&g_accp[js][(size_t)gi * NC32 + h * 8 + 4] = o1;
        g_zp[js][gi * NH + h] = s[8];
    }
}

// ---------------- 5) reduce j-splits, node embeddings + log_softmax ----------------
__global__ void k_fin1(float* __restrict__ dne, int write_ne) {
    int i = blockIdx.x * blockDim.x + threadIdx.x;
    float s[32], Z[4];
#pragma unroll
    for (int q = 0; q < 32; q++) s[q] = 0.f;
#pragma unroll
    for (int h = 0; h < 4; h++) Z[h] = 0.f;
#pragma unroll
    for (int js = 0; js < JS; js++) {
#pragma unroll
        for (int q4 = 0; q4 < 8; q4++) {
            float4 p = *(const float4*)&g_accp[js][(size_t)i * NC32 + q4 * 4];
            s[q4 * 4 + 0] += p.x; s[q4 * 4 + 1] += p.y;
            s[q4 * 4 + 2] += p.z; s[q4 * 4 + 3] += p.w;
        }
        float4 z = *(const float4*)&g_zp[js][i * NH];
        Z[0] += z.x; Z[1] += z.y; Z[2] += z.z; Z[3] += z.w;
    }
    float ne[8];
#pragma unroll
    for (int o = 0; o < 8; o++) ne[o] = 0.f;
#pragma unroll
    for (int h = 0; h < 4; h++) {
        float zi = 0.25f / fmaxf(Z[h], 1e-30f);
#pragma unroll
        for (int o = 0; o < 8; o++) ne[o] = fmaf(s[h * 8 + o], zi, ne[o]);
    }
    float m = ne[0];
#pragma unroll
    for (int o = 1; o < 8; o++) m = fmaxf(m, ne[o]);
    float sum = 0.f;
#pragma unroll
    for (int o = 0; o < 8; o++) sum += expf(ne[o] - m);
    float lse = logf(sum) + m;
#pragma unroll
    for (int o = 0; o < 8; o++) g_ls[(size_t)i * NO + o] = ne[o] - lse;
    if (write_ne) {
#pragma unroll
        for (int o = 0; o < 8; o++) dne[(size_t)i * NO + o] = ne[o];
    }
}

// ---------------- 6) out = ls.T @ w_lin.T + b ----------------
__global__ void k_fin2(const float* __restrict__ wl, const float* __restrict__ bl,
                       float* __restrict__ dout, int write_out) {
    __shared__ float rb[256][8];
    int t = threadIdx.x;
    float p[8];
#pragma unroll
    for (int o = 0; o < 8; o++) p[o] = 0.f;
    for (int i = t; i < NN; i += 256) {
        float wv = __ldg(wl + i);
        float4 l0 = *(const float4*)&g_ls[(size_t)i * NO];
        float4 l1 = *(const float4*)&g_ls[(size_t)i * NO + 4];
        p[0] = fmaf(l0.x, wv, p[0]); p[1] = fmaf(l0.y, wv, p[1]);
        p[2] = fmaf(l0.z, wv, p[2]); p[3] = fmaf(l0.w, wv, p[3]);
        p[4] = fmaf(l1.x, wv, p[4]); p[5] = fmaf(l1.y, wv, p[5]);
        p[6] = fmaf(l1.z, wv, p[6]); p[7] = fmaf(l1.w, wv, p[7]);
    }
#pragma unroll
    for (int o = 0; o < 8; o++) rb[t][o] = p[o];
    __syncthreads();
    if (t < 8 && write_out) {
        float s = 0.f;
        for (int q = 0; q < 256; q++) s += rb[q][t];
        dout[t] = s + __ldg(bl);
    }
}

// ---------------- launch ----------------
extern "C" void kernel_launch(void* const* d_in, const int* in_sizes, int n_in,
                              void* d_out, int out_size) {
    const float* x   = (const float*)d_in[0];
    const int*   adj = (const int*)d_in[1];
    const float* W   = (const float*)d_in[2];
    const float* a   = (const float*)d_in[3];
    const float* wl  = (const float*)d_in[4];
    const float* bl  = (const float*)d_in[5];
    float* outp = (float*)d_out;

    int write_out = 0, write_ne = 0, ne_off = 0;
    if (out_size >= 8 + NN * NO)      { write_out = 1; write_ne = 1; ne_off = 8; }
    else if (out_size == NN * NO)     { write_ne = 1; ne_off = 0; }
    else                              { write_out = 1; }

    k_pack<<<NN / 8, 256>>>(adj);
    dim3 gg(NN / 64, KS);
    k_gemm<<<gg, 256>>>(x, W);
    k_whfin<<<NN / 256, 256>>>(a);
    dim3 ga(NN / 32, JS);
    k_attn<<<ga, 256>>>();
    k_fin1<<<NN / 256, 256>>>(outp + ne_off, write_ne);
    k_fin2<<<1, 256>>>(wl, bl, outp, write_out);
}

// round 6
// speedup vs baseline: 2.4729x; 1.6202x over previous
#include <cuda_runtime.h>
#include <math.h>

#define NN 4096
#define NF 4096
#define NH 4
#define NO 8
#define NC32 32            // NH*NO
#define NW (NN/32)         // bitmask words per row = 128
#define JS 16              // j-splits for attention (grid.y)
#define KS 8               // k-splits for gemm
#define GAT_ALPHA 0.2f
#define L2E 1.44269504088896341f

// ---------------- scratch (__device__ globals; no allocations) ----------------
__device__ float         g_Cpart[KS][NN * NC32];  // k-split GEMM partials (4MB)
__device__ float         g_Wh[NN * NC32];         // Wh[j][h*8+o]  (512KB, L2-resident)
__device__ float         g_sdst4[NN * NH];        // s_dst[j][h]
__device__ float         g_ssrc4[NN * NH];        // s_src[i][h]
__device__ unsigned      g_bmT[NW * NN];          // bitmask, transposed: [jw][i] (2MB)
__device__ unsigned      g_maxsd[NH];             // global max of s_dst per head (keyed)
__device__ float         g_hp[NN * NC32];         // atomically accumulated h' numer (1MB)
__device__ float         g_z[NN * NH];            // atomically accumulated Z
__device__ float         g_ls[NN * NO];           // log_softmax(node_embeddings)

// ---------------- helpers ----------------
__device__ __forceinline__ void ffma2(unsigned long long& d, unsigned long long a,
                                      unsigned long long b) {
    asm("fma.rn.f32x2 %0, %1, %2, %0;" : "+l"(d) : "l"(a), "l"(b));
}
__device__ __forceinline__ unsigned long long pack2(float v) {
    unsigned long long r;
    asm("mov.b64 %0, {%1, %1};" : "=l"(r) : "f"(v));
    return r;
}
__device__ __forceinline__ unsigned long long packab(float a, float b) {
    unsigned long long r;
    asm("mov.b64 %0, {%1, %2};" : "=l"(r) : "f"(a), "f"(b));
    return r;
}
union U64F2 { unsigned long long u; float2 f; };

// monotonic float<->uint key for atomicMax over signed floats
__device__ __forceinline__ unsigned fkey(float f) {
    unsigned u = __float_as_uint(f);
    return (u & 0x80000000u) ? ~u : (u | 0x80000000u);
}
__device__ __forceinline__ float funkey(unsigned k) {
    return __uint_as_float((k & 0x80000000u) ? (k & 0x7FFFFFFFu) : ~k);
}

// ---------------- 1) pack adjacency; reset maxsd; zero atomic outputs ----------------
__global__ void k_pack(const int* __restrict__ adj) {
    int gt = blockIdx.x * 256 + threadIdx.x;          // 512*256 = 131072 = NN*NC32
    g_hp[gt] = 0.f;
    if (gt < NN * NH) g_z[gt] = 0.f;
    if (gt < NH) g_maxsd[gt] = 0u;

    int w = threadIdx.x >> 5, lane = threadIdx.x & 31;
    int i = blockIdx.x * 8 + w;
    const int* row = adj + (size_t)i * NN;
    for (int jw = 0; jw < NW; jw++) {
        int v = __ldg(row + jw * 32 + lane);
        unsigned word = __ballot_sync(0xffffffffu, v != 0);
        if (lane == 0) g_bmT[jw * NN + i] = word;
    }
}

// ---------------- 2) Wh = x @ Wc  (k-split x8, BM=64, f32x2 inner) ----------------
__global__ void k_gemm(const float* __restrict__ x, const float* __restrict__ W) {
    __shared__ float xs[64][40];
    __shared__ float ws[32][36];
    int t = threadIdx.x;
    int c = t & 31, rg = t >> 5;
    int row0 = blockIdx.x * 64;
    int kbase = blockIdx.y * (NF / KS);
    unsigned long long acc2a[8], acc2b[8];
#pragma unroll
    for (int r = 0; r < 8; r++) { acc2a[r] = 0ull; acc2b[r] = 0ull; }

    for (int kt = 0; kt < NF / KS; kt += 32) {
        int k0 = kbase + kt;
#pragma unroll
        for (int q = 0; q < 2; q++) {
            int s = t * 2 + q;
            int r = s >> 3, kq = s & 7;
            float4 v = __ldg((const float4*)(x + (size_t)(row0 + r) * NF + k0 + kq * 4));
            *(float4*)&xs[r][kq * 4] = v;
        }
        {
            int k = t >> 3, c4 = (t & 7) * 4;
            int h = c4 >> 3, o = c4 & 7;
            float4 v = __ldg((const float4*)(W + (size_t)h * NF * NO + (size_t)(k0 + k) * NO + o));
            *(float4*)&ws[k][c4] = v;
        }
        __syncthreads();
#pragma unroll
        for (int k4 = 0; k4 < 32; k4 += 4) {
            unsigned long long wp0 = packab(ws[k4][c],     ws[k4 + 1][c]);
            unsigned long long wp1 = packab(ws[k4 + 2][c], ws[k4 + 3][c]);
#pragma unroll
            for (int r = 0; r < 8; r++) {
                ulonglong2 xv = *(const ulonglong2*)&xs[rg * 8 + r][k4];
                ffma2(acc2a[r], xv.x, wp0);
                ffma2(acc2b[r], xv.y, wp1);
            }
        }
        __syncthreads();
    }
    float* outp = g_Cpart[blockIdx.y];
#pragma unroll
    for (int r = 0; r < 8; r++) {
        U64F2 a, b; a.u = acc2a[r]; b.u = acc2b[r];
        outp[(size_t)(row0 + rg * 8 + r) * NC32 + c] = (a.f.x + a.f.y) + (b.f.x + b.f.y);
    }
}

// ---------------- 3) reduce k-split partials; s_src/s_dst; global sd max ----------------
__global__ void k_whfin(const float* __restrict__ a) {
    int i = blockIdx.x * blockDim.x + threadIdx.x;   // one row per thread
    int lane = threadIdx.x & 31, w = threadIdx.x >> 5;
    float v[32];
#pragma unroll
    for (int c4 = 0; c4 < 8; c4++) {
        float4 s = make_float4(0.f, 0.f, 0.f, 0.f);
#pragma unroll
        for (int ks = 0; ks < KS; ks++) {
            float4 p = *(const float4*)&g_Cpart[ks][(size_t)i * NC32 + c4 * 4];
            s.x += p.x; s.y += p.y; s.z += p.z; s.w += p.w;
        }
        v[c4 * 4 + 0] = s.x; v[c4 * 4 + 1] = s.y; v[c4 * 4 + 2] = s.z; v[c4 * 4 + 3] = s.w;
        *(float4*)&g_Wh[(size_t)i * NC32 + c4 * 4] = s;
    }
    float sdv[NH];
#pragma unroll
    for (int h = 0; h < NH; h++) {
        float ss = 0.f, sd = 0.f;
#pragma unroll
        for (int o = 0; o < NO; o++) {
            float wv = v[h * 8 + o];
            ss = fmaf(wv, __ldg(a + h * 16 + o), ss);
            sd = fmaf(wv, __ldg(a + h * 16 + 8 + o), sd);
        }
        g_ssrc4[i * NH + h] = ss;
        g_sdst4[i * NH + h] = sd;
        sdv[h] = sd;
    }
    __shared__ float mred[NH][8];
#pragma unroll
    for (int h = 0; h < NH; h++) {
        float m = sdv[h];
#pragma unroll
        for (int off = 16; off > 0; off >>= 1)
            m = fmaxf(m, __shfl_xor_sync(0xffffffffu, m, off));
        if (lane == 0) mred[h][w] = m;
    }
    __syncthreads();
    if (threadIdx.x < NH) {
        int h = threadIdx.x;
        float m = mred[h][0];
#pragma unroll
        for (int ww = 1; ww < 8; ww++) m = fmaxf(m, mred[h][ww]);
        atomicMax(&g_maxsd[h], fkey(m));
    }
}

// ---------------- 4) main attention pass: smem-staged j-tiles ----------------
// grid (NN/128, JS), block 128.  Warp w owns i = bx*128 + w*32 + lane.
// Each block covers NW/JS = 8 bitmask words = 256 j, staged in 4 chunks of 64.
__global__ void __launch_bounds__(128, 6) k_attn() {
    __shared__ float s_wh[64 * 32];   // 8KB: Wh for 64 j's
    __shared__ float s_sd[64 * 4];    // 1KB: sd4 for 64 j's
    int lane = threadIdx.x & 31, w = threadIdx.x >> 5;
    int i = blockIdx.x * 128 + w * 32 + lane;
    int jw0 = blockIdx.y * (NW / JS);

    float ss[4], ml[4];
#pragma unroll
    for (int h = 0; h < 4; h++) {
        ss[h] = g_ssrc4[i * 4 + h];
        float M = funkey(g_maxsd[h]);      // global upper bound of sd (lrelu monotone)
        float e = ss[h] + M;
        e = fmaxf(e, GAT_ALPHA * e);
        ml[h] = e * L2E;
    }

    unsigned long long acc[4][4];
    float Z[4];
#pragma unroll
    for (int h = 0; h < 4; h++) {
        Z[h] = 0.f;
#pragma unroll
        for (int q = 0; q < 4; q++) acc[h][q] = 0ull;
    }

    for (int ch = 0; ch < (NW / JS) / 2; ch++) {       // 4 chunks of 64 j
        int jwc = jw0 + ch * 2;
        int j0 = jwc * 32;
        __syncthreads();                                // protect previous chunk
        {
            const float4* src = (const float4*)(g_Wh + (size_t)j0 * 32);
            float4* dst = (float4*)s_wh;
#pragma unroll
            for (int q = 0; q < 4; q++)
                dst[q * 128 + threadIdx.x] = src[q * 128 + threadIdx.x];
            if (threadIdx.x < 64)
                ((float4*)s_sd)[threadIdx.x] =
                    ((const float4*)(g_sdst4 + (size_t)j0 * 4))[threadIdx.x];
        }
        __syncthreads();
#pragma unroll
        for (int wseg = 0; wseg < 2; wseg++) {
            unsigned word = g_bmT[(jwc + wseg) * NN + i];
            int jb = wseg * 32;
#pragma unroll 8
            for (int b = 0; b < 32; b++) {
                int jj = jb + b;
                float4 sd = *(const float4*)&s_sd[jj * 4];  // LDS broadcast
                unsigned on = (word >> b) & 1u;
#pragma unroll
                for (int h = 0; h < 4; h++) {
                    float sdh = (h == 0) ? sd.x : (h == 1) ? sd.y : (h == 2) ? sd.z : sd.w;
                    float e = ss[h] + sdh;
                    e = fmaxf(e, GAT_ALPHA * e);            // leaky relu
                    float t = fmaf(e, L2E, -ml[h]);
                    float wt;
                    asm("ex2.approx.ftz.f32 %0, %1;" : "=f"(wt) : "f"(t));
                    wt = on ? wt : 0.0f;
                    Z[h] += wt;
                    unsigned long long w2 = pack2(wt);
                    const ulonglong2* wp = (const ulonglong2*)&s_wh[jj * 32 + h * 8];
                    ulonglong2 wa = wp[0];                  // LDS broadcast
                    ulonglong2 wb = wp[1];
                    ffma2(acc[h][0], w2, wa.x);
                    ffma2(acc[h][1], w2, wa.y);
                    ffma2(acc[h][2], w2, wb.x);
                    ffma2(acc[h][3], w2, wb.y);
                }
            }
        }
    }

    // per-lane direct atomic accumulation (warps own disjoint i)
    float* hp = g_hp + (size_t)i * NC32;
#pragma unroll
    for (int h = 0; h < 4; h++) {
#pragma unroll
        for (int q = 0; q < 4; q++) {
            U64F2 cv; cv.u = acc[h][q];
            atomicAdd(&hp[h * 8 + q * 2],     cv.f.x);
            atomicAdd(&hp[h * 8 + q * 2 + 1], cv.f.y);
        }
        atomicAdd(&g_z[i * 4 + h], Z[h]);
    }
}

// ---------------- 5) normalize, mean over heads, log_softmax ----------------
__global__ void k_fin1(float* __restrict__ dne, int write_ne) {
    int i = blockIdx.x * 64 + threadIdx.x;    // grid 64, block 64
    float4 z4 = *(const float4*)&g_z[i * 4];
    float zi[4] = { 0.25f / fmaxf(z4.x, 1e-30f), 0.25f / fmaxf(z4.y, 1e-30f),
                    0.25f / fmaxf(z4.z, 1e-30f), 0.25f / fmaxf(z4.w, 1e-30f) };
    float ne[8];
#pragma unroll
    for (int o = 0; o < 8; o++) ne[o] = 0.f;
#pragma unroll
    for (int h = 0; h < 4; h++) {
        float4 p0 = *(const float4*)&g_hp[(size_t)i * NC32 + h * 8];
        float4 p1 = *(const float4*)&g_hp[(size_t)i * NC32 + h * 8 + 4];
        ne[0] = fmaf(p0.x, zi[h], ne[0]); ne[1] = fmaf(p0.y, zi[h], ne[1]);
        ne[2] = fmaf(p0.z, zi[h], ne[2]); ne[3] = fmaf(p0.w, zi[h], ne[3]);
        ne[4] = fmaf(p1.x, zi[h], ne[4]); ne[5] = fmaf(p1.y, zi[h], ne[5]);
        ne[6] = fmaf(p1.z, zi[h], ne[6]); ne[7] = fmaf(p1.w, zi[h], ne[7]);
    }
    float m = ne[0];
#pragma unroll
    for (int o = 1; o < 8; o++) m = fmaxf(m, ne[o]);
    float sum = 0.f;
#pragma unroll
    for (int o = 0; o < 8; o++) sum += expf(ne[o] - m);
    float lse = logf(sum) + m;
#pragma unroll
    for (int o = 0; o < 8; o++) g_ls[(size_t)i * NO + o] = ne[o] - lse;
    if (write_ne) {
#pragma unroll
        for (int o = 0; o < 8; o++) dne[(size_t)i * NO + o] = ne[o];
    }
}

// ---------------- 6) out = ls.T @ w_lin.T + b ----------------
__global__ void k_fin2(const float* __restrict__ wl, const float* __restrict__ bl,
                       float* __restrict__ dout, int write_out) {
    __shared__ float rb[256][8];
    int t = threadIdx.x;
    float p[8];
#pragma unroll
    for (int o = 0; o < 8; o++) p[o] = 0.f;
    for (int i = t; i < NN; i += 256) {
        float wv = __ldg(wl + i);
        float4 l0 = *(const float4*)&g_ls[(size_t)i * NO];
        float4 l1 = *(const float4*)&g_ls[(size_t)i * NO + 4];
        p[0] = fmaf(l0.x, wv, p[0]); p[1] = fmaf(l0.y, wv, p[1]);
        p[2] = fmaf(l0.z, wv, p[2]); p[3] = fmaf(l0.w, wv, p[3]);
        p[4] = fmaf(l1.x, wv, p[4]); p[5] = fmaf(l1.y, wv, p[5]);
        p[6] = fmaf(l1.z, wv, p[6]); p[7] = fmaf(l1.w, wv, p[7]);
    }
#pragma unroll
    for (int o = 0; o < 8; o++) rb[t][o] = p[o];
    __syncthreads();
    if (t < 8 && write_out) {
        float s = 0.f;
        for (int q = 0; q < 256; q++) s += rb[q][t];
        dout[t] = s + __ldg(bl);
    }
}

// ---------------- launch ----------------
extern "C" void kernel_launch(void* const* d_in, const int* in_sizes, int n_in,
                              void* d_out, int out_size) {
    const float* x   = (const float*)d_in[0];
    const int*   adj = (const int*)d_in[1];
    const float* W   = (const float*)d_in[2];
    const float* a   = (const float*)d_in[3];
    const float* wl  = (const float*)d_in[4];
    const float* bl  = (const float*)d_in[5];
    float* outp = (float*)d_out;

    int write_out = 0, write_ne = 0, ne_off = 0;
    if (out_size >= 8 + NN * NO)      { write_out = 1; write_ne = 1; ne_off = 8; }
    else if (out_size == NN * NO)     { write_ne = 1; ne_off = 0; }
    else                              { write_out = 1; }

    k_pack<<<NN / 8, 256>>>(adj);
    dim3 gg(NN / 64, KS);
    k_gemm<<<gg, 256>>>(x, W);
    k_whfin<<<NN / 256, 256>>>(a);
    dim3 ga(NN / 128, JS);
    k_attn<<<ga, 128>>>();
    k_fin1<<<NN / 64, 64>>>(outp + ne_off, write_ne);
    k_fin2<<<1, 256>>>(wl, bl, outp, write_out);
}